// round 15
// baseline (speedup 1.0000x reference)
#include <cuda_runtime.h>
#include <cuda_fp16.h>
#include <cstdint>

#define EPSF 1e-5f
#define NND 256
#define DD  128
#define HH  512
#define NR  65536

// -------- scratch (device globals: allocation-free rule) --------
__device__ __align__(16) float g_edges[NR * DD];
__device__ float g_adj[NR];
__device__ float g_msgs[NR];
__device__ __align__(16) float g_nodes[NND * DD];
__device__ __align__(16) float g_P[NND * HH];
__device__ __align__(16) float g_Q[NND * HH];
// pre-swizzled fp16 weight tile images: [layer 0..2][chunk 0..3][128n][128k]
__device__ __align__(16) __half g_W1h[196608];
__device__ __align__(16) __half g_W2h[196608];

// ================= low-level helpers =================
__device__ __forceinline__ uint32_t smem_to_u32(const void* p) {
    uint32_t a;
    asm("{ .reg .u64 t; cvta.to.shared.u64 t, %1; cvt.u32.u64 %0, t; }" : "=r"(a) : "l"(p));
    return a;
}
__device__ __forceinline__ void ldsm_x4(uint32_t* r, uint32_t addr) {
    asm volatile("ldmatrix.sync.aligned.m8n8.x4.shared.b16 {%0,%1,%2,%3}, [%4];"
        : "=r"(r[0]), "=r"(r[1]), "=r"(r[2]), "=r"(r[3]) : "r"(addr));
}
__device__ __forceinline__ void mma16816h(float* c, const uint32_t* a, uint32_t b0, uint32_t b1) {
    asm volatile("mma.sync.aligned.m16n8k16.row.col.f32.f16.f16.f32 "
        "{%0,%1,%2,%3}, {%4,%5,%6,%7}, {%8,%9}, {%0,%1,%2,%3};"
        : "+f"(c[0]), "+f"(c[1]), "+f"(c[2]), "+f"(c[3])
        : "r"(a[0]), "r"(a[1]), "r"(a[2]), "r"(a[3]), "r"(b0), "r"(b1));
}
__device__ __forceinline__ void cpasync16(uint32_t dst, const void* src) {
    asm volatile("cp.async.cg.shared.global [%0], [%1], 16;" :: "r"(dst), "l"(src));
}
#define CP_COMMIT() asm volatile("cp.async.commit_group;" ::: "memory")
#define CP_WAIT0()  asm volatile("cp.async.wait_group 0;" ::: "memory")
__device__ __forceinline__ uint32_t packh(float a, float b) {
    __half2 h = __floats2half2_rn(a, b);
    return reinterpret_cast<uint32_t&>(h);
}
__device__ __host__ __forceinline__ uint32_t swz_off(int r, int k) {
    return (uint32_t)(r * 256 + ((((k >> 3) ^ (r & 7)) & 15) << 4) + (k & 7) * 2);
}

// ================= init (fused): nodes copy + edge embedding + weight prep =======
__global__ void k_init(const float* __restrict__ nodes_in,
                       const float* __restrict__ coords,
                       const float* __restrict__ w, const float* __restrict__ b,
                       const float* __restrict__ gg, const float* __restrict__ bb,
                       const float* __restrict__ eu1_w, const float* __restrict__ eu2_w) {
    if (blockIdx.x >= 8192) {
        int idx = (blockIdx.x - 8192) * 256 + threadIdx.x;   // < 393216
        int which = idx / 196608;
        int rem = idx - which * 196608;
        int l = rem >> 16;
        int e = rem & 65535;
        int chunk = e >> 14;
        int e2 = e & 16383;
        int n = e2 >> 7, k = e2 & 127;
        float v;
        if (which == 0) v = eu1_w[l * 196608 + k * 512 + chunk * 128 + n];
        else            v = eu2_w[l * 65536 + (chunk * 128 + k) * 128 + n];
        int dst = (l * 4 + chunk) * 16384 + (int)(swz_off(n, k) >> 1);
        if (which == 0) g_W1h[dst] = __float2half_rn(v);
        else            g_W2h[dst] = __float2half_rn(v);
        return;
    }
    if (blockIdx.x < 64) {
        int t = blockIdx.x * 256 + threadIdx.x;
        g_nodes[t] = nodes_in[t];
        g_nodes[t + 16384] = nodes_in[t + 16384];
    }
    int warp = threadIdx.x >> 5, lane = threadIdx.x & 31;
    int row = blockIdx.x * 8 + warp;
    int i = row >> 8, j = row & 255;
    float dx = coords[i*3+0] - coords[j*3+0];
    float dy = coords[i*3+1] - coords[j*3+1];
    float dz = coords[i*3+2] - coords[j*3+2];
    float sq = dx*dx + dy*dy + dz*dz;
    float dist = sq > 0.f ? sqrtf(sq) : 0.f;
    if (lane == 0) g_adj[row] = (dist < 10.f) ? 1.f : 0.f;
    float e[4]; float s = 0.f, ss = 0.f;
#pragma unroll
    for (int t = 0; t < 4; t++) {
        int d = lane + 32*t;
        e[t] = dist * w[d] + b[d];
        s += e[t]; ss += e[t]*e[t];
    }
#pragma unroll
    for (int o = 16; o; o >>= 1) {
        s  += __shfl_xor_sync(0xffffffffu, s, o);
        ss += __shfl_xor_sync(0xffffffffu, ss, o);
    }
    float mean = s * (1.f/128.f);
    float var  = ss * (1.f/128.f) - mean*mean;
    float rs   = rsqrtf(var + EPSF);
#pragma unroll
    for (int t = 0; t < 4; t++) {
        int d = lane + 32*t;
        float v = (e[t]-mean)*rs*gg[d] + bb[d];
        g_edges[row*DD + d] = fmaxf(v, 0.f);
    }
}

// standalone msgs (used only for the last layer)
__global__ void k_msgs() {
    int warp = threadIdx.x >> 5, lane = threadIdx.x & 31;
    int row = blockIdx.x * 8 + warp;
    int i = row >> 8;
    const float4* e4 = (const float4*)(g_edges + row*DD);
    const float4* n4 = (const float4*)(g_nodes + i*DD);
    float4 a = e4[lane], c = n4[lane];
    float s = a.x*c.x + a.y*c.y + a.z*c.z + a.w*c.w;
#pragma unroll
    for (int o = 16; o; o >>= 1) s += __shfl_xor_sync(0xffffffffu, s, o);
    if (lane == 0) g_msgs[row] = g_adj[row] * s;
}

// P/Q for layer 0; grid (64,2), 512 thr
__global__ void __launch_bounds__(512) k_pq(const float* __restrict__ Wp,
                                            const float* __restrict__ Wq) {
    __shared__ float xs[512];
    int tid = threadIdx.x;
    int r0 = blockIdx.x * 4;
    const float* __restrict__ W = blockIdx.y ? Wq : Wp;
    float* out = blockIdx.y ? g_Q : g_P;
    xs[tid] = g_nodes[r0 * 128 + tid];
    __syncthreads();
    float a0 = 0.f, a1 = 0.f, a2 = 0.f, a3 = 0.f;
    for (int kt = 0; kt < 128; kt += 4) {
        float w[4];
#pragma unroll
        for (int t = 0; t < 4; t++) w[t] = W[(kt + t) * 512 + tid];
#pragma unroll
        for (int t = 0; t < 4; t++) {
            int k = kt + t;
            a0 = fmaf(xs[k],       w[t], a0);
            a1 = fmaf(xs[128 + k], w[t], a1);
            a2 = fmaf(xs[256 + k], w[t], a2);
            a3 = fmaf(xs[384 + k], w[t], a3);
        }
    }
    out[(r0+0)*512 + tid] = a0;
    out[(r0+1)*512 + tid] = a1;
    out[(r0+2)*512 + tid] = a2;
    out[(r0+3)*512 + tid] = a3;
}

// ================= HMMA fused edge update: 2 CTAs/SM =================
// smem: y/h panels 4x16KB @0 (A aliased in panel 3), B 32KB @65536, params @98304
__global__ void __launch_bounds__(512, 2) k_edge_mma(int l,
        const float* __restrict__ b1, const float* __restrict__ gg,
        const float* __restrict__ bb, const float* __restrict__ b2) {
    extern __shared__ char sm[];
    const uint32_t S = smem_to_u32(sm);
    const int tid = threadIdx.x, lane = tid & 31;
    const int wM = (tid >> 5) & 1, wN = tid >> 6;
    const int row0 = blockIdx.x * 64;
    const int i = row0 >> 8, j0 = row0 & 255;

    const uint32_t Bb = S + 65536;
    float* Pb    = (float*)(sm + 98304);
    float* Gam   = (float*)(sm + 100352);
    float* Bet   = (float*)(sm + 102400);
    float* B2s   = (float*)(sm + 104448);
    float* redPS = (float*)(sm + 104960);   // [8][64]
    float* redPQ = (float*)(sm + 107008);   // [8][64]
    float* meanS = (float*)(sm + 109056);
    float* rstdS = (float*)(sm + 109312);

    Pb[tid]  = g_P[i*512 + tid] + b1[tid];
    Gam[tid] = gg[tid];
    Bet[tid] = bb[tid];
    if (tid < 128) B2s[tid] = b2[tid];

    const __half* W1b = g_W1h + l * 65536;
    const __half* W2b = g_W2h + l * 65536;
    auto fillB = [&](const __half* src) {
#pragma unroll
        for (int t = 0; t < 4; t++)
            cpasync16(Bb + (uint32_t)tid * 16 + (uint32_t)t * 8192,
                      (const char*)src + tid * 16 + t * 8192);
        CP_COMMIT();
    };
    fillB(W1b);   // chunk 0

    // A = edges tile -> fp16 panel 3; fused msgs from OLD edges
    {
        const int c4 = tid & 31, k0 = c4 * 4, rb = tid >> 5;
        const float4 nv = *(const float4*)&g_nodes[(size_t)i * 128 + k0];
#pragma unroll
        for (int t = 0; t < 4; t++) {
            int r = rb + t * 16;
            float4 v = *(const float4*)&g_edges[(size_t)(row0 + r) * 128 + k0];
            float dot = v.x*nv.x + v.y*nv.y + v.z*nv.z + v.w*nv.w;
#pragma unroll
            for (int o = 16; o; o >>= 1) dot += __shfl_xor_sync(0xffffffffu, dot, o);
            if (lane == 0) g_msgs[row0 + r] = g_adj[row0 + r] * dot;
            uint32_t off = 49152 + swz_off(r, k0);
            *(uint2*)(sm + off) = make_uint2(packh(v.x, v.y), packh(v.z, v.w));
        }
    }
    __syncthreads();

    const int aR  = wM * 32 + (lane & 15);
    const int aKx = lane >> 4;
    const int bR  = wN * 16 + (lane & 7) + ((lane & 16) >> 1);
    const int bKx = (lane & 8) >> 3;
    const int R = wM * 32 + (lane >> 2);
    const int colB = wN * 16 + (lane & 3) * 2;
    const uint32_t APan = S + 49152;

    float s4[4] = {0.f, 0.f, 0.f, 0.f}, q4[4] = {0.f, 0.f, 0.f, 0.f};

    // ---- GEMM1 in two N-halves (acc = 32 regs) ----
    for (int half = 0; half < 2; half++) {
        float acc[2][2][2][4];
#pragma unroll
        for (int a = 0; a < 2; a++)
#pragma unroll
            for (int b = 0; b < 2; b++)
#pragma unroll
                for (int c = 0; c < 2; c++)
#pragma unroll
                    for (int d = 0; d < 4; d++) acc[a][b][c][d] = 0.f;
        for (int ncl = 0; ncl < 2; ncl++) {
            int nc = half * 2 + ncl;
            CP_WAIT0();
            __syncthreads();
#pragma unroll
            for (int ks = 0; ks < 8; ks++) {
                uint32_t ah[2][4], bh[4];
#pragma unroll
                for (int mt = 0; mt < 2; mt++) {
                    int r = aR + mt * 16;
                    uint32_t off = (uint32_t)r * 256 + (uint32_t)((((ks * 2 + aKx) ^ (r & 7)) & 15) << 4);
                    ldsm_x4(ah[mt], APan + off);
                }
                {
                    uint32_t off = (uint32_t)bR * 256 + (uint32_t)((((ks * 2 + bKx) ^ (bR & 7)) & 15) << 4);
                    ldsm_x4(bh, Bb + off);
                }
#pragma unroll
                for (int mt = 0; mt < 2; mt++) {
                    mma16816h(acc[ncl][mt][0], ah[mt], bh[0], bh[1]);
                    mma16816h(acc[ncl][mt][1], ah[mt], bh[2], bh[3]);
                }
            }
            __syncthreads();
            fillB((nc < 3) ? (W1b + (nc + 1) * 16384) : W2b);
        }
        // epilogue for this half: y = acc + P + Q, partial LN sums, pack y->panels
#pragma unroll
        for (int ncl = 0; ncl < 2; ncl++) {
            int nc = half * 2 + ncl;
#pragma unroll
            for (int mt = 0; mt < 2; mt++)
#pragma unroll
                for (int nt = 0; nt < 2; nt++) {
                    int col = nc * 128 + colB + nt * 8;
                    int rA = j0 + R + mt * 16;
                    float2 qa = *(const float2*)&g_Q[(size_t)rA * 512 + col];
                    float2 qb = *(const float2*)&g_Q[(size_t)(rA + 8) * 512 + col];
                    float p0 = Pb[col], p1 = Pb[col + 1];
                    float* a = acc[ncl][mt][nt];
                    a[0] += p0 + qa.x; a[1] += p1 + qa.y;
                    a[2] += p0 + qb.x; a[3] += p1 + qb.y;
                    s4[mt*2+0] += a[0] + a[1]; q4[mt*2+0] += a[0]*a[0] + a[1]*a[1];
                    s4[mt*2+1] += a[2] + a[3]; q4[mt*2+1] += a[2]*a[2] + a[3]*a[3];
                    int kl = colB + nt * 8;
                    int r1 = R + mt * 16, r2 = r1 + 8;
                    *(uint32_t*)(sm + nc * 16384 + swz_off(r1, kl)) = packh(a[0], a[1]);
                    *(uint32_t*)(sm + nc * 16384 + swz_off(r2, kl)) = packh(a[2], a[3]);
                }
        }
    }

    // ---- LN stats reduce ----
#pragma unroll
    for (int o = 1; o <= 2; o <<= 1)
#pragma unroll
        for (int t = 0; t < 4; t++) {
            s4[t] += __shfl_xor_sync(0xffffffffu, s4[t], o);
            q4[t] += __shfl_xor_sync(0xffffffffu, q4[t], o);
        }
    if ((lane & 3) == 0) {
#pragma unroll
        for (int t = 0; t < 4; t++) {
            int rr = R + (t >> 1) * 16 + (t & 1) * 8;
            redPS[wN * 64 + rr] = s4[t];
            redPQ[wN * 64 + rr] = q4[t];
        }
    }
    __syncthreads();
    if (tid < 64) {
        float Ssum = 0.f, Qsum = 0.f;
#pragma unroll
        for (int p = 0; p < 8; p++) {
            Ssum += redPS[p * 64 + tid];
            Qsum += redPQ[p * 64 + tid];
        }
        float mean = Ssum * (1.f / 512.f);
        float var = Qsum * (1.f / 512.f) - mean * mean;
        meanS[tid] = mean;
        rstdS[tid] = rsqrtf(var + EPSF);
    }
    __syncthreads();
    float mn[4], rs[4];
#pragma unroll
    for (int t = 0; t < 4; t++) {
        int rr = R + (t >> 1) * 16 + (t & 1) * 8;
        mn[t] = meanS[rr]; rs[t] = rstdS[rr];
    }

    // ---- h-ify panels in place: h = relu(LN(y)) ----
#pragma unroll
    for (int nc = 0; nc < 4; nc++)
#pragma unroll
        for (int mt = 0; mt < 2; mt++)
#pragma unroll
            for (int nt = 0; nt < 2; nt++) {
                int kl = colB + nt * 8;
                int col = nc * 128 + kl;
                float g0 = Gam[col], g1 = Gam[col + 1];
                float be0 = Bet[col], be1 = Bet[col + 1];
                int r1 = R + mt * 16, r2 = r1 + 8;
                uint32_t* a1 = (uint32_t*)(sm + nc * 16384 + swz_off(r1, kl));
                uint32_t* a2 = (uint32_t*)(sm + nc * 16384 + swz_off(r2, kl));
                __half2 yh1 = *(__half2*)a1;
                __half2 yh2 = *(__half2*)a2;
                float y0 = __low2float(yh1), y1 = __high2float(yh1);
                float y2 = __low2float(yh2), y3 = __high2float(yh2);
                *a1 = packh(fmaxf((y0 - mn[mt*2])   * rs[mt*2]   * g0 + be0, 0.f),
                            fmaxf((y1 - mn[mt*2])   * rs[mt*2]   * g1 + be1, 0.f));
                *a2 = packh(fmaxf((y2 - mn[mt*2+1]) * rs[mt*2+1] * g0 + be0, 0.f),
                            fmaxf((y3 - mn[mt*2+1]) * rs[mt*2+1] * g1 + be1, 0.f));
            }
    __syncthreads();

    // ---- GEMM2: 4 kc, single B buffer, serially refilled ----
    float acc2[2][2][4];
#pragma unroll
    for (int b = 0; b < 2; b++)
#pragma unroll
        for (int c = 0; c < 2; c++)
#pragma unroll
            for (int d = 0; d < 4; d++) acc2[b][c][d] = 0.f;

    for (int kc = 0; kc < 4; kc++) {
        CP_WAIT0();
        __syncthreads();
        const uint32_t AHp = S + (uint32_t)kc * 16384;
#pragma unroll
        for (int ks = 0; ks < 8; ks++) {
            uint32_t ah[2][4], bh[4];
#pragma unroll
            for (int mt = 0; mt < 2; mt++) {
                int r = aR + mt * 16;
                uint32_t off = (uint32_t)r * 256 + (uint32_t)((((ks * 2 + aKx) ^ (r & 7)) & 15) << 4);
                ldsm_x4(ah[mt], AHp + off);
            }
            {
                uint32_t off = (uint32_t)bR * 256 + (uint32_t)((((ks * 2 + bKx) ^ (bR & 7)) & 15) << 4);
                ldsm_x4(bh, Bb + off);
            }
#pragma unroll
            for (int mt = 0; mt < 2; mt++) {
                mma16816h(acc2[mt][0], ah[mt], bh[0], bh[1]);
                mma16816h(acc2[mt][1], ah[mt], bh[2], bh[3]);
            }
        }
        __syncthreads();
        if (kc < 3) fillB(W2b + (kc + 1) * 16384);
    }

    // ---- output: acc2 + residual + b2 ----
#pragma unroll
    for (int mt = 0; mt < 2; mt++)
#pragma unroll
        for (int nt = 0; nt < 2; nt++) {
            int col = colB + nt * 8;
            int r1 = row0 + R + mt * 16;
            float b20 = B2s[col], b21 = B2s[col + 1];
            float2 e0 = *(const float2*)&g_edges[(size_t)r1 * 128 + col];
            float2 e1 = *(const float2*)&g_edges[(size_t)(r1 + 8) * 128 + col];
            float* a = acc2[mt][nt];
            *(float2*)&g_edges[(size_t)r1 * 128 + col] =
                make_float2(a[0] + e0.x + b20, a[1] + e0.y + b21);
            *(float2*)&g_edges[(size_t)(r1 + 8) * 128 + col] =
                make_float2(a[2] + e1.x + b20, a[3] + e1.y + b21);
        }
}

// ================= node MLP: 1024 threads, batched loads, BM=4, grid 64 =========
__global__ void __launch_bounds__(1024, 1) k_node(
        const float* __restrict__ W1, const float* __restrict__ b1,
        const float* __restrict__ gg, const float* __restrict__ bb,
        const float* __restrict__ W2, const float* __restrict__ b2,
        const float* __restrict__ Wp, const float* __restrict__ Wq, int do_pq) {
    __shared__ float Xs[4 * 384];
    __shared__ float BUF[8192];
    __shared__ float red[128];
    __shared__ float fin[8];
    __shared__ float mS[4], rS[4];
    __shared__ float Xn[512];
    const int tid = threadIdx.x, lane = tid & 31, wid = tid >> 5;
    const int r0 = blockIdx.x * 4;
    {
        int row = tid >> 8, c = tid & 255;
        Xs[row * 384 + 128 + c] = g_msgs[(r0 + row) * 256 + c];
        if (tid < 512) {
            int rw = tid >> 7, cc = tid & 127;
            Xs[rw * 384 + cc] = g_nodes[(r0 + rw) * 128 + cc];
        }
    }
    __syncthreads();
    {
        int ks = tid >> 8, cp = tid & 255;
        int kb = ks * 96;
        float a[8];
#pragma unroll
        for (int t = 0; t < 8; t++) a[t] = 0.f;
        for (int kt = 0; kt < 96; kt += 4) {
            float2 w[4];
#pragma unroll
            for (int t = 0; t < 4; t++)
                w[t] = *(const float2*)&W1[(size_t)(kb + kt + t) * 512 + cp * 2];
#pragma unroll
            for (int t = 0; t < 4; t++) {
                int k = kb + kt + t;
                float x0 = Xs[k], x1 = Xs[384 + k], x2 = Xs[768 + k], x3 = Xs[1152 + k];
                a[0] = fmaf(x0, w[t].x, a[0]); a[1] = fmaf(x0, w[t].y, a[1]);
                a[2] = fmaf(x1, w[t].x, a[2]); a[3] = fmaf(x1, w[t].y, a[3]);
                a[4] = fmaf(x2, w[t].x, a[4]); a[5] = fmaf(x2, w[t].y, a[5]);
                a[6] = fmaf(x3, w[t].x, a[6]); a[7] = fmaf(x3, w[t].y, a[7]);
            }
        }
        float* pg = BUF + ks * 2048 + cp * 2;
        pg[0] = a[0];    pg[1] = a[1];
        pg[512] = a[2];  pg[513] = a[3];
        pg[1024] = a[4]; pg[1025] = a[5];
        pg[1536] = a[6]; pg[1537] = a[7];
    }
    __syncthreads();
    const int col = tid & 511, rp = tid >> 9;
    float y0, y1;
    {
        int rA = 2 * rp, rB = rA + 1;
        float bv = b1[col];
        y0 = BUF[rA*512+col] + BUF[2048+rA*512+col] + BUF[4096+rA*512+col] + BUF[6144+rA*512+col] + bv;
        y1 = BUF[rB*512+col] + BUF[2048+rB*512+col] + BUF[4096+rB*512+col] + BUF[6144+rB*512+col] + bv;
        float s0 = y0, q0 = y0*y0, s1 = y1, q1 = y1*y1;
#pragma unroll
        for (int o = 16; o; o >>= 1) {
            s0 += __shfl_xor_sync(0xffffffffu, s0, o);
            q0 += __shfl_xor_sync(0xffffffffu, q0, o);
            s1 += __shfl_xor_sync(0xffffffffu, s1, o);
            q1 += __shfl_xor_sync(0xffffffffu, q1, o);
        }
        if (lane == 0) {
            red[wid*4+0] = s0; red[wid*4+1] = q0; red[wid*4+2] = s1; red[wid*4+3] = q1;
        }
    }
    __syncthreads();
    if (tid < 8) {
        int r = tid >> 1, sq = tid & 1;
        int grp = r >> 1, within = r & 1;
        float v = 0.f;
#pragma unroll
        for (int w = 0; w < 16; w++) v += red[(grp * 16 + w) * 4 + within * 2 + sq];
        fin[tid] = v;
    }
    __syncthreads();
    if (tid < 4) {
        float mean = fin[tid*2] * (1.f/512.f);
        float var = fin[tid*2+1] * (1.f/512.f) - mean*mean;
        mS[tid] = mean;
        rS[tid] = rsqrtf(var + EPSF);
    }
    __syncthreads();
    {
        float gv = gg[col], btv = bb[col];
        int rA = 2*rp, rB = rA + 1;
        float* Hs = BUF + 4096;
        Hs[rA*512+col] = fmaxf((y0 - mS[rA]) * rS[rA] * gv + btv, 0.f);
        Hs[rB*512+col] = fmaxf((y1 - mS[rB]) * rS[rB] * gv + btv, 0.f);
    }
    __syncthreads();
    {
        const float* Hs = BUF + 4096;
        int ks = tid >> 7, c2 = tid & 127;
        int kb = ks * 64;
        float o0 = 0, o1 = 0, o2 = 0, o3 = 0;
        for (int kt = 0; kt < 64; kt += 4) {
            float w[4];
#pragma unroll
            for (int t = 0; t < 4; t++)
                w[t] = W2[(size_t)(kb + kt + t) * 128 + c2];
#pragma unroll
            for (int t = 0; t < 4; t++) {
                int k = kb + kt + t;
                o0 = fmaf(Hs[k], w[t], o0);        o1 = fmaf(Hs[512 + k], w[t], o1);
                o2 = fmaf(Hs[1024 + k], w[t], o2); o3 = fmaf(Hs[1536 + k], w[t], o3);
            }
        }
        float* pg = BUF + ks * 512;
        pg[c2] = o0; pg[128 + c2] = o1; pg[256 + c2] = o2; pg[384 + c2] = o3;
    }
    __syncthreads();
    if (tid < 512) {
        int row = tid >> 7, c = tid & 127;
        float v = 0.f;
#pragma unroll
        for (int s = 0; s < 8; s++) v += BUF[s * 512 + row * 128 + c];
        v += g_nodes[(r0 + row) * 128 + c] + b2[c];
        g_nodes[(r0 + row) * 128 + c] = v;
        Xn[row * 128 + c] = v;
    }
    if (do_pq) {
        __syncthreads();
        const float* W = (tid >> 9) ? Wq : Wp;
        float* out = (tid >> 9) ? g_Q : g_P;
        float a0 = 0, a1 = 0, a2 = 0, a3 = 0;
        for (int kt = 0; kt < 128; kt += 4) {
            float w[4];
#pragma unroll
            for (int t = 0; t < 4; t++)
                w[t] = W[(size_t)(kt + t) * 512 + col];
#pragma unroll
            for (int t = 0; t < 4; t++) {
                int k = kt + t;
                a0 = fmaf(Xn[k], w[t], a0);
                a1 = fmaf(Xn[128 + k], w[t], a1);
                a2 = fmaf(Xn[256 + k], w[t], a2);
                a3 = fmaf(Xn[384 + k], w[t], a3);
            }
        }
        out[(size_t)(r0 + 0) * 512 + col] = a0;
        out[(size_t)(r0 + 1) * 512 + col] = a1;
        out[(size_t)(r0 + 2) * 512 + col] = a2;
        out[(size_t)(r0 + 3) * 512 + col] = a3;
    }
}

// ---- 512-thr 4-row LN-MLP stage (KD=128) ----
__device__ __forceinline__ void stage128(const float* Xs, float* Hs, float* part, float* red,
        const float* __restrict__ W1, const float* __restrict__ b1,
        const float* __restrict__ gg, const float* __restrict__ bb,
        int tid, int lane, int wid) {
    {
        int ks = tid >> 8, cp = tid & 255;
        float a00=0,a01=0,a10=0,a11=0,a20=0,a21=0,a30=0,a31=0;
        int kb = ks * 64;
#pragma unroll 8
        for (int kk = 0; kk < 64; kk++) {
            int k = kb + kk;
            float2 w = *(const float2*)&W1[(size_t)k * 512 + cp * 2];
            float x0 = Xs[k], x1 = Xs[128 + k], x2 = Xs[256 + k], x3 = Xs[384 + k];
            a00 = fmaf(x0, w.x, a00); a01 = fmaf(x0, w.y, a01);
            a10 = fmaf(x1, w.x, a10); a11 = fmaf(x1, w.y, a11);
            a20 = fmaf(x2, w.x, a20); a21 = fmaf(x2, w.y, a21);
            a30 = fmaf(x3, w.x, a30); a31 = fmaf(x3, w.y, a31);
        }
        float* pg = part + ks * 2048 + cp * 2;
        pg[0] = a00;    pg[1] = a01;
        pg[512] = a10;  pg[513] = a11;
        pg[1024] = a20; pg[1025] = a21;
        pg[1536] = a30; pg[1537] = a31;
    }
    __syncthreads();
    float y0, y1, y2, y3;
    {
        float bv = b1[tid];
        y0 = part[tid]        + part[2048 + tid]        + bv;
        y1 = part[512 + tid]  + part[2048 + 512 + tid]  + bv;
        y2 = part[1024 + tid] + part[2048 + 1024 + tid] + bv;
        y3 = part[1536 + tid] + part[2048 + 1536 + tid] + bv;
    }
    {
        float s0=y0,s1=y1,s2=y2,s3=y3,q0=y0*y0,q1=y1*y1,q2=y2*y2,q3=y3*y3;
#pragma unroll
        for (int o = 16; o; o >>= 1) {
            s0 += __shfl_xor_sync(0xffffffffu, s0, o);
            s1 += __shfl_xor_sync(0xffffffffu, s1, o);
            s2 += __shfl_xor_sync(0xffffffffu, s2, o);
            s3 += __shfl_xor_sync(0xffffffffu, s3, o);
            q0 += __shfl_xor_sync(0xffffffffu, q0, o);
            q1 += __shfl_xor_sync(0xffffffffu, q1, o);
            q2 += __shfl_xor_sync(0xffffffffu, q2, o);
            q3 += __shfl_xor_sync(0xffffffffu, q3, o);
        }
        if (lane == 0) {
            float* rw = red + wid * 8;
            rw[0]=s0; rw[1]=s1; rw[2]=s2; rw[3]=s3; rw[4]=q0; rw[5]=q1; rw[6]=q2; rw[7]=q3;
        }
    }
    __syncthreads();
    if (tid < 8) {
        float v = 0.f;
#pragma unroll
        for (int w = 0; w < 16; w++) v += red[w * 8 + tid];
        red[128 + tid] = v;
    }
    __syncthreads();
    {
        float gv = gg[tid], btv = bb[tid];
        float m0 = red[128] * (1.f/512.f), m1 = red[129] * (1.f/512.f);
        float m2 = red[130] * (1.f/512.f), m3 = red[131] * (1.f/512.f);
        float rs0 = rsqrtf(red[132] * (1.f/512.f) - m0*m0 + EPSF);
        float rs1 = rsqrtf(red[133] * (1.f/512.f) - m1*m1 + EPSF);
        float rs2 = rsqrtf(red[134] * (1.f/512.f) - m2*m2 + EPSF);
        float rs3 = rsqrtf(red[135] * (1.f/512.f) - m3*m3 + EPSF);
        Hs[tid]        = fmaxf((y0 - m0) * rs0 * gv + btv, 0.f);
        Hs[512 + tid]  = fmaxf((y1 - m1) * rs1 * gv + btv, 0.f);
        Hs[1024 + tid] = fmaxf((y2 - m2) * rs2 * gv + btv, 0.f);
        Hs[1536 + tid] = fmaxf((y3 - m3) * rs3 * gv + btv, 0.f);
    }
    __syncthreads();
}

// final output head; BM=4, grid 64, 512 thr
__global__ void __launch_bounds__(512, 1) k_final(
        const float* __restrict__ no1_w, const float* __restrict__ no1_b,
        const float* __restrict__ no_g,  const float* __restrict__ no_bt,
        const float* __restrict__ no2_w, const float* __restrict__ no2_b,
        const float* __restrict__ sp1_w, const float* __restrict__ sp1_b,
        const float* __restrict__ sp_g,  const float* __restrict__ sp_bt,
        const float* __restrict__ sp2_w, const float* __restrict__ sp2_b,
        float* __restrict__ out_nodes, float* __restrict__ out_coords) {
    __shared__ float Xs[512];
    __shared__ float Hs[4 * 512];
    __shared__ float part[4096];
    __shared__ float red[136];
    __shared__ float X2[512];
    const int tid = threadIdx.x, lane = tid & 31, wid = tid >> 5;
    const int r0 = blockIdx.x * 4;
    {
        int row = tid >> 7, c = tid & 127;
        Xs[row * 128 + c] = g_nodes[(r0 + row) * 128 + c];
    }
    __syncthreads();
    stage128(Xs, Hs, part, red, no1_w, no1_b, no_g, no_bt, tid, lane, wid);
    {
        int ks = tid >> 7, col = tid & 127;
        float o0=0,o1=0,o2=0,o3=0;
        int kb = ks * 128;
#pragma unroll 8
        for (int kk = 0; kk < 128; kk++) {
            int k = kb + kk;
            float w = no2_w[(size_t)k * 128 + col];
            o0 = fmaf(Hs[k], w, o0);        o1 = fmaf(Hs[512 + k], w, o1);
            o2 = fmaf(Hs[1024 + k], w, o2); o3 = fmaf(Hs[1536 + k], w, o3);
        }
        float* pg = part + ks * 512 + col;
        pg[0] = o0; pg[128] = o1; pg[256] = o2; pg[384] = o3;
    }
    __syncthreads();
    {
        int row = tid >> 7, c = tid & 127;
        float v = part[row * 128 + c] + part[512 + row * 128 + c]
                + part[1024 + row * 128 + c] + part[1536 + row * 128 + c] + no2_b[c];
        out_nodes[(r0 + row) * 128 + c] = v;
        X2[row * 128 + c] = v;
    }
    __syncthreads();
    stage128(X2, Hs, part, red, sp1_w, sp1_b, sp_g, sp_bt, tid, lane, wid);
    int g = tid >> 4;
    if (g < 12) {
        int row = g / 3, cc = g - row * 3;
        int l16 = tid & 15;
        float s = 0.f;
        for (int k = l16; k < 512; k += 16) s = fmaf(Hs[row * 512 + k], sp2_w[k * 3 + cc], s);
#pragma unroll
        for (int o = 8; o; o >>= 1) s += __shfl_xor_sync(0xffffffffu, s, o);
        if (l16 == 0) out_coords[(r0 + row) * 3 + cc] = s + sp2_b[cc];
    }
}

// ================= launcher =================
extern "C" void kernel_launch(void* const* d_in, const int* in_sizes, int n_in,
                              void* d_out, int out_size) {
    const float* nodes  = (const float*)d_in[0];
    const float* coords = (const float*)d_in[1];
    const float* ee_w   = (const float*)d_in[2];
    const float* ee_b   = (const float*)d_in[3];
    const float* ee_g   = (const float*)d_in[4];
    const float* ee_bt  = (const float*)d_in[5];
    const float* nu1_w  = (const float*)d_in[6];
    const float* nu1_b  = (const float*)d_in[7];
    const float* nu_g   = (const float*)d_in[8];
    const float* nu_bt  = (const float*)d_in[9];
    const float* nu2_w  = (const float*)d_in[10];
    const float* nu2_b  = (const float*)d_in[11];
    const float* eu1_w  = (const float*)d_in[12];
    const float* eu1_b  = (const float*)d_in[13];
    const float* eu_g   = (const float*)d_in[14];
    const float* eu_bt  = (const float*)d_in[15];
    const float* eu2_w  = (const float*)d_in[16];
    const float* eu2_b  = (const float*)d_in[17];
    const float* sp1_w  = (const float*)d_in[18];
    const float* sp1_b  = (const float*)d_in[19];
    const float* sp_g   = (const float*)d_in[20];
    const float* sp_bt  = (const float*)d_in[21];
    const float* sp2_w  = (const float*)d_in[22];
    const float* sp2_b  = (const float*)d_in[23];
    const float* no1_w  = (const float*)d_in[24];
    const float* no1_b  = (const float*)d_in[25];
    const float* no_g   = (const float*)d_in[26];
    const float* no_bt  = (const float*)d_in[27];
    const float* no2_w  = (const float*)d_in[28];
    const float* no2_b  = (const float*)d_in[29];
    float* out = (float*)d_out;

    const int SME = 109568;
    cudaFuncSetAttribute(k_edge_mma, cudaFuncAttributeMaxDynamicSharedMemorySize, SME);

    k_init<<<9728, 256>>>(nodes, coords, ee_w, ee_b, ee_g, ee_bt, eu1_w, eu2_w);  // 0
    k_pq<<<dim3(64, 2), 512>>>(eu1_w + 65536, eu1_w + 131072);                    // 1

    for (int l = 0; l < 3; l++) {
        k_edge_mma<<<1024, 512, SME>>>(l, eu1_b + l*512, eu_g + l*512,   // 2 (l=0)
                                       eu_bt + l*512, eu2_b + l*128);
        int do_pq = (l < 2) ? 1 : 0;
        const float* Wp = eu1_w + (l+1)*196608 + 65536;
        const float* Wq = eu1_w + (l+1)*196608 + 131072;
        k_node<<<64, 1024>>>(nu1_w + l*196608, nu1_b + l*512,            // 3 (l=0)
                             nu_g + l*512, nu_bt + l*512,
                             nu2_w + l*65536, nu2_b + l*128,
                             Wp, Wq, do_pq);
    }
    // layer 3: edge output is dead code — msgs only
    k_msgs<<<8192, 256>>>();
    k_node<<<64, 1024>>>(nu1_w + 3*196608, nu1_b + 3*512,
                         nu_g + 3*512, nu_bt + 3*512,
                         nu2_w + 3*65536, nu2_b + 3*128,
                         nu1_w, nu1_w, 0);
    k_final<<<64, 512>>>(no1_w, no1_b, no_g, no_bt, no2_w, no2_b,
                         sp1_w, sp1_b, sp_g, sp_bt, sp2_w, sp2_b,
                         out, out + 32768);
}

// round 16
// speedup vs baseline: 1.1167x; 1.1167x over previous
#include <cuda_runtime.h>
#include <cuda_fp16.h>
#include <cstdint>

#define EPSF 1e-5f
#define NND 256
#define DD  128
#define HH  512
#define NR  65536

// -------- scratch (device globals: allocation-free rule) --------
__device__ __align__(16) float g_edges[NR * DD];
__device__ float g_adj[NR];
__device__ float g_msgs[NR];
__device__ __align__(16) float g_nodes[NND * DD];
__device__ __align__(16) float g_P[NND * HH];
__device__ __align__(16) float g_Q[NND * HH];
// pre-swizzled fp16 weight tile images: [layer 0..2][chunk 0..3][128n][128k]
__device__ __align__(16) __half g_W1h[196608];
__device__ __align__(16) __half g_W2h[196608];

// ================= low-level helpers =================
__device__ __forceinline__ uint32_t smem_to_u32(const void* p) {
    uint32_t a;
    asm("{ .reg .u64 t; cvta.to.shared.u64 t, %1; cvt.u32.u64 %0, t; }" : "=r"(a) : "l"(p));
    return a;
}
__device__ __forceinline__ void ldsm_x4(uint32_t* r, uint32_t addr) {
    asm volatile("ldmatrix.sync.aligned.m8n8.x4.shared.b16 {%0,%1,%2,%3}, [%4];"
        : "=r"(r[0]), "=r"(r[1]), "=r"(r[2]), "=r"(r[3]) : "r"(addr));
}
__device__ __forceinline__ void mma16816h(float* c, const uint32_t* a, uint32_t b0, uint32_t b1) {
    asm volatile("mma.sync.aligned.m16n8k16.row.col.f32.f16.f16.f32 "
        "{%0,%1,%2,%3}, {%4,%5,%6,%7}, {%8,%9}, {%0,%1,%2,%3};"
        : "+f"(c[0]), "+f"(c[1]), "+f"(c[2]), "+f"(c[3])
        : "r"(a[0]), "r"(a[1]), "r"(a[2]), "r"(a[3]), "r"(b0), "r"(b1));
}
__device__ __forceinline__ void cpasync16(uint32_t dst, const void* src) {
    asm volatile("cp.async.cg.shared.global [%0], [%1], 16;" :: "r"(dst), "l"(src));
}
#define CP_COMMIT() asm volatile("cp.async.commit_group;" ::: "memory")
#define CP_WAIT0()  asm volatile("cp.async.wait_group 0;" ::: "memory")
__device__ __forceinline__ void pair_bar(int wN) {
    asm volatile("bar.sync %0, 64;" :: "r"(1 + wN) : "memory");
}
__device__ __forceinline__ uint32_t packh(float a, float b) {
    __half2 h = __floats2half2_rn(a, b);
    return reinterpret_cast<uint32_t&>(h);
}
__device__ __host__ __forceinline__ uint32_t swz_off(int r, int k) {
    return (uint32_t)(r * 256 + ((((k >> 3) ^ (r & 7)) & 15) << 4) + (k & 7) * 2);
}

// ================= init (fused): nodes copy + edge embedding + weight prep =======
__global__ void k_init(const float* __restrict__ nodes_in,
                       const float* __restrict__ coords,
                       const float* __restrict__ w, const float* __restrict__ b,
                       const float* __restrict__ gg, const float* __restrict__ bb,
                       const float* __restrict__ eu1_w, const float* __restrict__ eu2_w) {
    if (blockIdx.x >= 8192) {
        int idx = (blockIdx.x - 8192) * 256 + threadIdx.x;   // < 393216
        int which = idx / 196608;
        int rem = idx - which * 196608;
        int l = rem >> 16;
        int e = rem & 65535;
        int chunk = e >> 14;
        int e2 = e & 16383;
        int n = e2 >> 7, k = e2 & 127;
        float v;
        if (which == 0) v = eu1_w[l * 196608 + k * 512 + chunk * 128 + n];
        else            v = eu2_w[l * 65536 + (chunk * 128 + k) * 128 + n];
        int dst = (l * 4 + chunk) * 16384 + (int)(swz_off(n, k) >> 1);
        if (which == 0) g_W1h[dst] = __float2half_rn(v);
        else            g_W2h[dst] = __float2half_rn(v);
        return;
    }
    if (blockIdx.x < 64) {
        int t = blockIdx.x * 256 + threadIdx.x;
        g_nodes[t] = nodes_in[t];
        g_nodes[t + 16384] = nodes_in[t + 16384];
    }
    int warp = threadIdx.x >> 5, lane = threadIdx.x & 31;
    int row = blockIdx.x * 8 + warp;
    int i = row >> 8, j = row & 255;
    float dx = coords[i*3+0] - coords[j*3+0];
    float dy = coords[i*3+1] - coords[j*3+1];
    float dz = coords[i*3+2] - coords[j*3+2];
    float sq = dx*dx + dy*dy + dz*dz;
    float dist = sq > 0.f ? sqrtf(sq) : 0.f;
    if (lane == 0) g_adj[row] = (dist < 10.f) ? 1.f : 0.f;
    float e[4]; float s = 0.f, ss = 0.f;
#pragma unroll
    for (int t = 0; t < 4; t++) {
        int d = lane + 32*t;
        e[t] = dist * w[d] + b[d];
        s += e[t]; ss += e[t]*e[t];
    }
#pragma unroll
    for (int o = 16; o; o >>= 1) {
        s  += __shfl_xor_sync(0xffffffffu, s, o);
        ss += __shfl_xor_sync(0xffffffffu, ss, o);
    }
    float mean = s * (1.f/128.f);
    float var  = ss * (1.f/128.f) - mean*mean;
    float rs   = rsqrtf(var + EPSF);
#pragma unroll
    for (int t = 0; t < 4; t++) {
        int d = lane + 32*t;
        float v = (e[t]-mean)*rs*gg[d] + bb[d];
        g_edges[row*DD + d] = fmaxf(v, 0.f);
    }
}

// standalone msgs (used only for the last layer)
__global__ void k_msgs() {
    int warp = threadIdx.x >> 5, lane = threadIdx.x & 31;
    int row = blockIdx.x * 8 + warp;
    int i = row >> 8;
    const float4* e4 = (const float4*)(g_edges + row*DD);
    const float4* n4 = (const float4*)(g_nodes + i*DD);
    float4 a = e4[lane], c = n4[lane];
    float s = a.x*c.x + a.y*c.y + a.z*c.z + a.w*c.w;
#pragma unroll
    for (int o = 16; o; o >>= 1) s += __shfl_xor_sync(0xffffffffu, s, o);
    if (lane == 0) g_msgs[row] = g_adj[row] * s;
}

// P/Q for layer 0; grid (64,2), 512 thr
__global__ void __launch_bounds__(512) k_pq(const float* __restrict__ Wp,
                                            const float* __restrict__ Wq) {
    __shared__ float xs[512];
    int tid = threadIdx.x;
    int r0 = blockIdx.x * 4;
    const float* __restrict__ W = blockIdx.y ? Wq : Wp;
    float* out = blockIdx.y ? g_Q : g_P;
    xs[tid] = g_nodes[r0 * 128 + tid];
    __syncthreads();
    float a0 = 0.f, a1 = 0.f, a2 = 0.f, a3 = 0.f;
    for (int kt = 0; kt < 128; kt += 4) {
        float w[4];
#pragma unroll
        for (int t = 0; t < 4; t++) w[t] = W[(kt + t) * 512 + tid];
#pragma unroll
        for (int t = 0; t < 4; t++) {
            int k = kt + t;
            a0 = fmaf(xs[k],       w[t], a0);
            a1 = fmaf(xs[128 + k], w[t], a1);
            a2 = fmaf(xs[256 + k], w[t], a2);
            a3 = fmaf(xs[384 + k], w[t], a3);
        }
    }
    out[(r0+0)*512 + tid] = a0;
    out[(r0+1)*512 + tid] = a1;
    out[(r0+2)*512 + tid] = a2;
    out[(r0+3)*512 + tid] = a3;
}

// ================= HMMA fused edge update (R10-12 proven version) =====
// smem bytes: h/A panels 4x16KB @0, B 4x32KB @65536, params @196608
__global__ void __launch_bounds__(512, 1) k_edge_mma(int l,
        const float* __restrict__ b1, const float* __restrict__ gg,
        const float* __restrict__ bb, const float* __restrict__ b2) {
    extern __shared__ char sm[];
    const uint32_t S = smem_to_u32(sm);
    const int tid = threadIdx.x, lane = tid & 31;
    const int wM = (tid >> 5) & 1, wN = tid >> 6;
    const int row0 = blockIdx.x * 64;
    const int i = row0 >> 8, j0 = row0 & 255;

    const uint32_t BBs = S + 65536;       // 4 bufs x 32KB
    float* Pb    = (float*)(sm + 196608);
    float* Gam   = (float*)(sm + 198656);
    float* Bet   = (float*)(sm + 200704);
    float* B2s   = (float*)(sm + 202752);
    float* redPS = (float*)(sm + 203264);   // [8][64]
    float* redPQ = (float*)(sm + 205312);   // [8][64]
    float* meanS = (float*)(sm + 207360);
    float* rstdS = (float*)(sm + 207616);

    Pb[tid]  = g_P[i*512 + tid] + b1[tid];
    Gam[tid] = gg[tid];
    Bet[tid] = bb[tid];
    if (tid < 128) B2s[tid] = b2[tid];

    const int pid = tid & 63;
    auto fillw = [&](int buf, const __half* sW) {
        uint32_t d = BBs + (uint32_t)buf * 32768 + (uint32_t)wN * 4096;
        const char* g = (const char*)sW + wN * 4096;
#pragma unroll
        for (int t = 0; t < 4; t++) {
            uint32_t byo = (uint32_t)(pid + t * 64) * 16;
            cpasync16(d + byo, g + byo);
        }
        CP_COMMIT();
    };
    const __half* W1b = g_W1h + l * 65536;
    const __half* W2b = g_W2h + l * 65536;
    fillw(0, W1b); fillw(1, W1b + 16384); fillw(2, W1b + 32768); fillw(3, W1b + 49152);

    // A = edges tile -> fp16 panel 0; fused msgs from OLD edges
    {
        const int c4 = tid & 31, k0 = c4 * 4, rb = tid >> 5;
        const float4 nv = *(const float4*)&g_nodes[(size_t)i * 128 + k0];
        float4 v[4];
#pragma unroll
        for (int t = 0; t < 4; t++)
            v[t] = *(const float4*)&g_edges[(size_t)(row0 + rb + t * 16) * 128 + k0];
#pragma unroll
        for (int t = 0; t < 4; t++) {
            int r = rb + t * 16;
            float dot = v[t].x*nv.x + v[t].y*nv.y + v[t].z*nv.z + v[t].w*nv.w;
#pragma unroll
            for (int o = 16; o; o >>= 1) dot += __shfl_xor_sync(0xffffffffu, dot, o);
            if (lane == 0) g_msgs[row0 + r] = g_adj[row0 + r] * dot;
            uint32_t off = swz_off(r, k0);
            *(uint2*)(sm + off) = make_uint2(packh(v[t].x, v[t].y), packh(v[t].z, v[t].w));
        }
    }
    __syncthreads();

    // ---- GEMM1: ks-outer, A fragments reused across all 4 N-chunks ----
    float acc1[4][2][2][4];
#pragma unroll
    for (int a = 0; a < 4; a++)
#pragma unroll
        for (int b = 0; b < 2; b++)
#pragma unroll
            for (int c = 0; c < 2; c++)
#pragma unroll
                for (int d = 0; d < 4; d++) acc1[a][b][c][d] = 0.f;

    const int aR  = wM * 32 + (lane & 15);
    const int aKx = lane >> 4;
    const int bR  = wN * 16 + (lane & 7) + ((lane & 16) >> 1);
    const int bKx = (lane & 8) >> 3;

    CP_WAIT0();
    pair_bar(wN);
#pragma unroll
    for (int ks = 0; ks < 8; ks++) {
        uint32_t ah[2][4];
#pragma unroll
        for (int mt = 0; mt < 2; mt++) {
            int r = aR + mt * 16;
            uint32_t off = (uint32_t)r * 256 + (uint32_t)((((ks * 2 + aKx) ^ (r & 7)) & 15) << 4);
            ldsm_x4(ah[mt], S + off);
        }
        uint32_t boff = (uint32_t)bR * 256 + (uint32_t)((((ks * 2 + bKx) ^ (bR & 7)) & 15) << 4);
#pragma unroll
        for (int nc = 0; nc < 4; nc++) {
            uint32_t bh[4];
            ldsm_x4(bh, BBs + (uint32_t)nc * 32768 + boff);
#pragma unroll
            for (int mt = 0; mt < 2; mt++) {
                mma16816h(acc1[nc][mt][0], ah[mt], bh[0], bh[1]);
                mma16816h(acc1[nc][mt][1], ah[mt], bh[2], bh[3]);
            }
        }
    }
    pair_bar(wN);
    fillw(0, W2b); fillw(1, W2b + 16384); fillw(2, W2b + 32768); fillw(3, W2b + 49152);

    // ---- epilogue: y = acc + P + Q, LN stats ----
    const int R = wM * 32 + (lane >> 2);
    const int colB = wN * 16 + (lane & 3) * 2;
    float s4[4] = {0.f, 0.f, 0.f, 0.f}, q4[4] = {0.f, 0.f, 0.f, 0.f};
#pragma unroll
    for (int nc = 0; nc < 4; nc++)
#pragma unroll
        for (int mt = 0; mt < 2; mt++)
#pragma unroll
            for (int nt = 0; nt < 2; nt++) {
                int col = nc * 128 + colB + nt * 8;
                int rA = j0 + R + mt * 16;
                float2 qa = *(const float2*)&g_Q[(size_t)rA * 512 + col];
                float2 qb = *(const float2*)&g_Q[(size_t)(rA + 8) * 512 + col];
                float p0 = Pb[col], p1 = Pb[col + 1];
                float* a = acc1[nc][mt][nt];
                a[0] += p0 + qa.x; a[1] += p1 + qa.y;
                a[2] += p0 + qb.x; a[3] += p1 + qb.y;
                s4[mt*2+0] += a[0] + a[1]; q4[mt*2+0] += a[0]*a[0] + a[1]*a[1];
                s4[mt*2+1] += a[2] + a[3]; q4[mt*2+1] += a[2]*a[2] + a[3]*a[3];
            }
#pragma unroll
    for (int o = 1; o <= 2; o <<= 1)
#pragma unroll
        for (int t = 0; t < 4; t++) {
            s4[t] += __shfl_xor_sync(0xffffffffu, s4[t], o);
            q4[t] += __shfl_xor_sync(0xffffffffu, q4[t], o);
        }
    if ((lane & 3) == 0) {
#pragma unroll
        for (int t = 0; t < 4; t++) {
            int rr = R + (t >> 1) * 16 + (t & 1) * 8;
            redPS[wN * 64 + rr] = s4[t];
            redPQ[wN * 64 + rr] = q4[t];
        }
    }
    __syncthreads();
    if (tid < 64) {
        float Ssum = 0.f, Qsum = 0.f;
#pragma unroll
        for (int p = 0; p < 8; p++) {
            Ssum += redPS[p * 64 + tid];
            Qsum += redPQ[p * 64 + tid];
        }
        float mean = Ssum * (1.f / 512.f);
        float var = Qsum * (1.f / 512.f) - mean * mean;
        meanS[tid] = mean;
        rstdS[tid] = rsqrtf(var + EPSF);
    }
    __syncthreads();
    float mn[4], rs[4];
#pragma unroll
    for (int t = 0; t < 4; t++) {
        int rr = R + (t >> 1) * 16 + (t & 1) * 8;
        mn[t] = meanS[rr]; rs[t] = rstdS[rr];
    }

    // ---- stage ALL normalized h chunks into 4 panels, one sync ----
#pragma unroll
    for (int kc = 0; kc < 4; kc++) {
        const uint32_t pb = (uint32_t)kc * 16384;
#pragma unroll
        for (int mt = 0; mt < 2; mt++)
#pragma unroll
            for (int nt = 0; nt < 2; nt++) {
                int col = kc * 128 + colB + nt * 8;
                float g0 = Gam[col], g1 = Gam[col + 1];
                float be0 = Bet[col], be1 = Bet[col + 1];
                float* a = acc1[kc][mt][nt];
                float h0 = fmaxf((a[0] - mn[mt*2])   * rs[mt*2]   * g0 + be0, 0.f);
                float h1 = fmaxf((a[1] - mn[mt*2])   * rs[mt*2]   * g1 + be1, 0.f);
                float h2 = fmaxf((a[2] - mn[mt*2+1]) * rs[mt*2+1] * g0 + be0, 0.f);
                float h3 = fmaxf((a[3] - mn[mt*2+1]) * rs[mt*2+1] * g1 + be1, 0.f);
                int kl = colB + nt * 8;
                int r1 = R + mt * 16, r2 = r1 + 8;
                *(uint32_t*)(sm + pb + swz_off(r1, kl)) = packh(h0, h1);
                *(uint32_t*)(sm + pb + swz_off(r2, kl)) = packh(h2, h3);
            }
    }
    CP_WAIT0();
    __syncthreads();

    // prefetch residual (hidden under GEMM2)
    float2 e0r[2][2], e1r[2][2];
#pragma unroll
    for (int mt = 0; mt < 2; mt++)
#pragma unroll
        for (int nt = 0; nt < 2; nt++) {
            int col = colB + nt * 8;
            int r1 = row0 + R + mt * 16;
            e0r[mt][nt] = *(const float2*)&g_edges[(size_t)r1 * 128 + col];
            e1r[mt][nt] = *(const float2*)&g_edges[(size_t)(r1 + 8) * 128 + col];
        }

    // ---- GEMM2: barrier-free ----
    float acc2[2][2][4];
#pragma unroll
    for (int b = 0; b < 2; b++)
#pragma unroll
        for (int c = 0; c < 2; c++)
#pragma unroll
            for (int d = 0; d < 4; d++) acc2[b][c][d] = 0.f;

#pragma unroll
    for (int kc = 0; kc < 4; kc++) {
        const uint32_t AHp = S + (uint32_t)kc * 16384;
        const uint32_t BH = BBs + (uint32_t)kc * 32768;
#pragma unroll
        for (int ks = 0; ks < 8; ks++) {
            uint32_t ah[2][4], bh[4];
#pragma unroll
            for (int mt = 0; mt < 2; mt++) {
                int r = aR + mt * 16;
                uint32_t off = (uint32_t)r * 256 + (uint32_t)((((ks * 2 + aKx) ^ (r & 7)) & 15) << 4);
                ldsm_x4(ah[mt], AHp + off);
            }
            {
                uint32_t off = (uint32_t)bR * 256 + (uint32_t)((((ks * 2 + bKx) ^ (bR & 7)) & 15) << 4);
                ldsm_x4(bh, BH + off);
            }
#pragma unroll
            for (int mt = 0; mt < 2; mt++) {
                mma16816h(acc2[mt][0], ah[mt], bh[0], bh[1]);
                mma16816h(acc2[mt][1], ah[mt], bh[2], bh[3]);
            }
        }
    }

    // ---- output: acc2 + residual + b2 ----
#pragma unroll
    for (int mt = 0; mt < 2; mt++)
#pragma unroll
        for (int nt = 0; nt < 2; nt++) {
            int col = colB + nt * 8;
            int r1 = row0 + R + mt * 16;
            float b20 = B2s[col], b21 = B2s[col + 1];
            float* a = acc2[mt][nt];
            *(float2*)&g_edges[(size_t)r1 * 128 + col] =
                make_float2(a[0] + e0r[mt][nt].x + b20, a[1] + e0r[mt][nt].y + b21);
            *(float2*)&g_edges[(size_t)(r1 + 8) * 128 + col] =
                make_float2(a[2] + e1r[mt][nt].x + b20, a[3] + e1r[mt][nt].y + b21);
        }
}

// ================= node MLP: 1024 threads (R14 proven), BM=4, grid 64 =========
__global__ void __launch_bounds__(1024, 1) k_node(
        const float* __restrict__ W1, const float* __restrict__ b1,
        const float* __restrict__ gg, const float* __restrict__ bb,
        const float* __restrict__ W2, const float* __restrict__ b2,
        const float* __restrict__ Wp, const float* __restrict__ Wq, int do_pq) {
    __shared__ float Xs[4 * 384];
    __shared__ float BUF[8192];
    __shared__ float red[128];
    __shared__ float fin[8];
    __shared__ float mS[4], rS[4];
    __shared__ float Xn[512];
    const int tid = threadIdx.x, lane = tid & 31, wid = tid >> 5;
    const int r0 = blockIdx.x * 4;
    {
        int row = tid >> 8, c = tid & 255;
        Xs[row * 384 + 128 + c] = g_msgs[(r0 + row) * 256 + c];
        if (tid < 512) {
            int rw = tid >> 7, cc = tid & 127;
            Xs[rw * 384 + cc] = g_nodes[(r0 + rw) * 128 + cc];
        }
    }
    __syncthreads();
    {
        int ks = tid >> 8, cp = tid & 255;
        int kb = ks * 96;
        float a[8];
#pragma unroll
        for (int t = 0; t < 8; t++) a[t] = 0.f;
        for (int kt = 0; kt < 96; kt += 4) {
            float2 w[4];
#pragma unroll
            for (int t = 0; t < 4; t++)
                w[t] = *(const float2*)&W1[(size_t)(kb + kt + t) * 512 + cp * 2];
#pragma unroll
            for (int t = 0; t < 4; t++) {
                int k = kb + kt + t;
                float x0 = Xs[k], x1 = Xs[384 + k], x2 = Xs[768 + k], x3 = Xs[1152 + k];
                a[0] = fmaf(x0, w[t].x, a[0]); a[1] = fmaf(x0, w[t].y, a[1]);
                a[2] = fmaf(x1, w[t].x, a[2]); a[3] = fmaf(x1, w[t].y, a[3]);
                a[4] = fmaf(x2, w[t].x, a[4]); a[5] = fmaf(x2, w[t].y, a[5]);
                a[6] = fmaf(x3, w[t].x, a[6]); a[7] = fmaf(x3, w[t].y, a[7]);
            }
        }
        float* pg = BUF + ks * 2048 + cp * 2;
        pg[0] = a[0];    pg[1] = a[1];
        pg[512] = a[2];  pg[513] = a[3];
        pg[1024] = a[4]; pg[1025] = a[5];
        pg[1536] = a[6]; pg[1537] = a[7];
    }
    __syncthreads();
    const int col = tid & 511, rp = tid >> 9;
    float y0, y1;
    {
        int rA = 2 * rp, rB = rA + 1;
        float bv = b1[col];
        y0 = BUF[rA*512+col] + BUF[2048+rA*512+col] + BUF[4096+rA*512+col] + BUF[6144+rA*512+col] + bv;
        y1 = BUF[rB*512+col] + BUF[2048+rB*512+col] + BUF[4096+rB*512+col] + BUF[6144+rB*512+col] + bv;
        float s0 = y0, q0 = y0*y0, s1 = y1, q1 = y1*y1;
#pragma unroll
        for (int o = 16; o; o >>= 1) {
            s0 += __shfl_xor_sync(0xffffffffu, s0, o);
            q0 += __shfl_xor_sync(0xffffffffu, q0, o);
            s1 += __shfl_xor_sync(0xffffffffu, s1, o);
            q1 += __shfl_xor_sync(0xffffffffu, q1, o);
        }
        if (lane == 0) {
            red[wid*4+0] = s0; red[wid*4+1] = q0; red[wid*4+2] = s1; red[wid*4+3] = q1;
        }
    }
    __syncthreads();
    if (tid < 8) {
        int r = tid >> 1, sq = tid & 1;
        int grp = r >> 1, within = r & 1;
        float v = 0.f;
#pragma unroll
        for (int w = 0; w < 16; w++) v += red[(grp * 16 + w) * 4 + within * 2 + sq];
        fin[tid] = v;
    }
    __syncthreads();
    if (tid < 4) {
        float mean = fin[tid*2] * (1.f/512.f);
        float var = fin[tid*2+1] * (1.f/512.f) - mean*mean;
        mS[tid] = mean;
        rS[tid] = rsqrtf(var + EPSF);
    }
    __syncthreads();
    {
        float gv = gg[col], btv = bb[col];
        int rA = 2*rp, rB = rA + 1;
        float* Hs = BUF + 4096;
        Hs[rA*512+col] = fmaxf((y0 - mS[rA]) * rS[rA] * gv + btv, 0.f);
        Hs[rB*512+col] = fmaxf((y1 - mS[rB]) * rS[rB] * gv + btv, 0.f);
    }
    __syncthreads();
    {
        const float* Hs = BUF + 4096;
        int ks = tid >> 7, c2 = tid & 127;
        int kb = ks * 64;
        float o0 = 0, o1 = 0, o2 = 0, o3 = 0;
        for (int kt = 0; kt < 64; kt += 4) {
            float w[4];
#pragma unroll
            for (int t = 0; t < 4; t++)
                w[t] = W2[(size_t)(kb + kt + t) * 128 + c2];
#pragma unroll
            for (int t = 0; t < 4; t++) {
                int k = kb + kt + t;
                o0 = fmaf(Hs[k], w[t], o0);        o1 = fmaf(Hs[512 + k], w[t], o1);
                o2 = fmaf(Hs[1024 + k], w[t], o2); o3 = fmaf(Hs[1536 + k], w[t], o3);
            }
        }
        float* pg = BUF + ks * 512;
        pg[c2] = o0; pg[128 + c2] = o1; pg[256 + c2] = o2; pg[384 + c2] = o3;
    }
    __syncthreads();
    if (tid < 512) {
        int row = tid >> 7, c = tid & 127;
        float v = 0.f;
#pragma unroll
        for (int s = 0; s < 8; s++) v += BUF[s * 512 + row * 128 + c];
        v += g_nodes[(r0 + row) * 128 + c] + b2[c];
        g_nodes[(r0 + row) * 128 + c] = v;
        Xn[row * 128 + c] = v;
    }
    if (do_pq) {
        __syncthreads();
        const float* W = (tid >> 9) ? Wq : Wp;
        float* out = (tid >> 9) ? g_Q : g_P;
        float a0 = 0, a1 = 0, a2 = 0, a3 = 0;
        for (int kt = 0; kt < 128; kt += 4) {
            float w[4];
#pragma unroll
            for (int t = 0; t < 4; t++)
                w[t] = W[(size_t)(kt + t) * 512 + col];
#pragma unroll
            for (int t = 0; t < 4; t++) {
                int k = kt + t;
                a0 = fmaf(Xn[k], w[t], a0);
                a1 = fmaf(Xn[128 + k], w[t], a1);
                a2 = fmaf(Xn[256 + k], w[t], a2);
                a3 = fmaf(Xn[384 + k], w[t], a3);
            }
        }
        out[(size_t)(r0 + 0) * 512 + col] = a0;
        out[(size_t)(r0 + 1) * 512 + col] = a1;
        out[(size_t)(r0 + 2) * 512 + col] = a2;
        out[(size_t)(r0 + 3) * 512 + col] = a3;
    }
}

// ---- 512-thr 4-row LN-MLP stage (KD=128), R12 proven ----
__device__ __forceinline__ void stage128(const float* Xs, float* Hs, float* part, float* red,
        const float* __restrict__ W1, const float* __restrict__ b1,
        const float* __restrict__ gg, const float* __restrict__ bb,
        int tid, int lane, int wid) {
    {
        int ks = tid >> 8, cp = tid & 255;
        float a00=0,a01=0,a10=0,a11=0,a20=0,a21=0,a30=0,a31=0;
        int kb = ks * 64;
#pragma unroll 8
        for (int kk = 0; kk < 64; kk++) {
            int k = kb + kk;
            float2 w = *(const float2*)&W1[(size_t)k * 512 + cp * 2];
            float x0 = Xs[k], x1 = Xs[128 + k], x2 = Xs[256 + k], x3 = Xs[384 + k];
            a00 = fmaf(x0, w.x, a00); a01 = fmaf(x0, w.y, a01);
            a10 = fmaf(x1, w.x, a10); a11 = fmaf(x1, w.y, a11);
            a20 = fmaf(x2, w.x, a20); a21 = fmaf(x2, w.y, a21);
            a30 = fmaf(x3, w.x, a30); a31 = fmaf(x3, w.y, a31);
        }
        float* pg = part + ks * 2048 + cp * 2;
        pg[0] = a00;    pg[1] = a01;
        pg[512] = a10;  pg[513] = a11;
        pg[1024] = a20; pg[1025] = a21;
        pg[1536] = a30; pg[1537] = a31;
    }
    __syncthreads();
    float y0, y1, y2, y3;
    {
        float bv = b1[tid];
        y0 = part[tid]        + part[2048 + tid]        + bv;
        y1 = part[512 + tid]  + part[2048 + 512 + tid]  + bv;
        y2 = part[1024 + tid] + part[2048 + 1024 + tid] + bv;
        y3 = part[1536 + tid] + part[2048 + 1536 + tid] + bv;
    }
    {
        float s0=y0,s1=y1,s2=y2,s3=y3,q0=y0*y0,q1=y1*y1,q2=y2*y2,q3=y3*y3;
#pragma unroll
        for (int o = 16; o; o >>= 1) {
            s0 += __shfl_xor_sync(0xffffffffu, s0, o);
            s1 += __shfl_xor_sync(0xffffffffu, s1, o);
            s2 += __shfl_xor_sync(0xffffffffu, s2, o);
            s3 += __shfl_xor_sync(0xffffffffu, s3, o);
            q0 += __shfl_xor_sync(0xffffffffu, q0, o);
            q1 += __shfl_xor_sync(0xffffffffu, q1, o);
            q2 += __shfl_xor_sync(0xffffffffu, q2, o);
            q3 += __shfl_xor_sync(0xffffffffu, q3, o);
        }
        if (lane == 0) {
            float* rw = red + wid * 8;
            rw[0]=s0; rw[1]=s1; rw[2]=s2; rw[3]=s3; rw[4]=q0; rw[5]=q1; rw[6]=q2; rw[7]=q3;
        }
    }
    __syncthreads();
    if (tid < 8) {
        float v = 0.f;
#pragma unroll
        for (int w = 0; w < 16; w++) v += red[w * 8 + tid];
        red[128 + tid] = v;
    }
    __syncthreads();
    {
        float gv = gg[tid], btv = bb[tid];
        float m0 = red[128] * (1.f/512.f), m1 = red[129] * (1.f/512.f);
        float m2 = red[130] * (1.f/512.f), m3 = red[131] * (1.f/512.f);
        float rs0 = rsqrtf(red[132] * (1.f/512.f) - m0*m0 + EPSF);
        float rs1 = rsqrtf(red[133] * (1.f/512.f) - m1*m1 + EPSF);
        float rs2 = rsqrtf(red[134] * (1.f/512.f) - m2*m2 + EPSF);
        float rs3 = rsqrtf(red[135] * (1.f/512.f) - m3*m3 + EPSF);
        Hs[tid]        = fmaxf((y0 - m0) * rs0 * gv + btv, 0.f);
        Hs[512 + tid]  = fmaxf((y1 - m1) * rs1 * gv + btv, 0.f);
        Hs[1024 + tid] = fmaxf((y2 - m2) * rs2 * gv + btv, 0.f);
        Hs[1536 + tid] = fmaxf((y3 - m3) * rs3 * gv + btv, 0.f);
    }
    __syncthreads();
}

// final output head; BM=4, grid 64, 512 thr (R12 proven)
__global__ void __launch_bounds__(512, 1) k_final(
        const float* __restrict__ no1_w, const float* __restrict__ no1_b,
        const float* __restrict__ no_g,  const float* __restrict__ no_bt,
        const float* __restrict__ no2_w, const float* __restrict__ no2_b,
        const float* __restrict__ sp1_w, const float* __restrict__ sp1_b,
        const float* __restrict__ sp_g,  const float* __restrict__ sp_bt,
        const float* __restrict__ sp2_w, const float* __restrict__ sp2_b,
        float* __restrict__ out_nodes, float* __restrict__ out_coords) {
    __shared__ float Xs[512];
    __shared__ float Hs[4 * 512];
    __shared__ float part[4096];
    __shared__ float red[136];
    __shared__ float X2[512];
    const int tid = threadIdx.x, lane = tid & 31, wid = tid >> 5;
    const int r0 = blockIdx.x * 4;
    {
        int row = tid >> 7, c = tid & 127;
        Xs[row * 128 + c] = g_nodes[(r0 + row) * 128 + c];
    }
    __syncthreads();
    stage128(Xs, Hs, part, red, no1_w, no1_b, no_g, no_bt, tid, lane, wid);
    {
        int ks = tid >> 7, col = tid & 127;
        float o0=0,o1=0,o2=0,o3=0;
        int kb = ks * 128;
#pragma unroll 8
        for (int kk = 0; kk < 128; kk++) {
            int k = kb + kk;
            float w = no2_w[(size_t)k * 128 + col];
            o0 = fmaf(Hs[k], w, o0);        o1 = fmaf(Hs[512 + k], w, o1);
            o2 = fmaf(Hs[1024 + k], w, o2); o3 = fmaf(Hs[1536 + k], w, o3);
        }
        float* pg = part + ks * 512 + col;
        pg[0] = o0; pg[128] = o1; pg[256] = o2; pg[384] = o3;
    }
    __syncthreads();
    {
        int row = tid >> 7, c = tid & 127;
        float v = part[row * 128 + c] + part[512 + row * 128 + c]
                + part[1024 + row * 128 + c] + part[1536 + row * 128 + c] + no2_b[c];
        out_nodes[(r0 + row) * 128 + c] = v;
        X2[row * 128 + c] = v;
    }
    __syncthreads();
    stage128(X2, Hs, part, red, sp1_w, sp1_b, sp_g, sp_bt, tid, lane, wid);
    int g = tid >> 4;
    if (g < 12) {
        int row = g / 3, cc = g - row * 3;
        int l16 = tid & 15;
        float s = 0.f;
        for (int k = l16; k < 512; k += 16) s = fmaf(Hs[row * 512 + k], sp2_w[k * 3 + cc], s);
#pragma unroll
        for (int o = 8; o; o >>= 1) s += __shfl_xor_sync(0xffffffffu, s, o);
        if (l16 == 0) out_coords[(r0 + row) * 3 + cc] = s + sp2_b[cc];
    }
}

// ================= launcher =================
extern "C" void kernel_launch(void* const* d_in, const int* in_sizes, int n_in,
                              void* d_out, int out_size) {
    const float* nodes  = (const float*)d_in[0];
    const float* coords = (const float*)d_in[1];
    const float* ee_w   = (const float*)d_in[2];
    const float* ee_b   = (const float*)d_in[3];
    const float* ee_g   = (const float*)d_in[4];
    const float* ee_bt  = (const float*)d_in[5];
    const float* nu1_w  = (const float*)d_in[6];
    const float* nu1_b  = (const float*)d_in[7];
    const float* nu_g   = (const float*)d_in[8];
    const float* nu_bt  = (const float*)d_in[9];
    const float* nu2_w  = (const float*)d_in[10];
    const float* nu2_b  = (const float*)d_in[11];
    const float* eu1_w  = (const float*)d_in[12];
    const float* eu1_b  = (const float*)d_in[13];
    const float* eu_g   = (const float*)d_in[14];
    const float* eu_bt  = (const float*)d_in[15];
    const float* eu2_w  = (const float*)d_in[16];
    const float* eu2_b  = (const float*)d_in[17];
    const float* sp1_w  = (const float*)d_in[18];
    const float* sp1_b  = (const float*)d_in[19];
    const float* sp_g   = (const float*)d_in[20];
    const float* sp_bt  = (const float*)d_in[21];
    const float* sp2_w  = (const float*)d_in[22];
    const float* sp2_b  = (const float*)d_in[23];
    const float* no1_w  = (const float*)d_in[24];
    const float* no1_b  = (const float*)d_in[25];
    const float* no_g   = (const float*)d_in[26];
    const float* no_bt  = (const float*)d_in[27];
    const float* no2_w  = (const float*)d_in[28];
    const float* no2_b  = (const float*)d_in[29];
    float* out = (float*)d_out;

    const int SME = 207872;
    cudaFuncSetAttribute(k_edge_mma, cudaFuncAttributeMaxDynamicSharedMemorySize, SME);

    k_init<<<9728, 256>>>(nodes, coords, ee_w, ee_b, ee_g, ee_bt, eu1_w, eu2_w);  // 0
    k_pq<<<dim3(64, 2), 512>>>(eu1_w + 65536, eu1_w + 131072);                    // 1

    for (int l = 0; l < 3; l++) {
        k_edge_mma<<<1024, 512, SME>>>(l, eu1_b + l*512, eu_g + l*512,   // 2 (l=0)
                                       eu_bt + l*512, eu2_b + l*128);
        int do_pq = (l < 2) ? 1 : 0;
        const float* Wp = eu1_w + (l+1)*196608 + 65536;
        const float* Wq = eu1_w + (l+1)*196608 + 131072;
        k_node<<<64, 1024>>>(nu1_w + l*196608, nu1_b + l*512,            // 3 (l=0)
                             nu_g + l*512, nu_bt + l*512,
                             nu2_w + l*65536, nu2_b + l*128,
                             Wp, Wq, do_pq);
    }
    // layer 3: edge output is dead code — msgs only
    k_msgs<<<8192, 256>>>();
    k_node<<<64, 1024>>>(nu1_w + 3*196608, nu1_b + 3*512,
                         nu_g + 3*512, nu_bt + 3*512,
                         nu2_w + 3*65536, nu2_b + 3*128,
                         nu1_w, nu1_w, 0);
    k_final<<<64, 512>>>(no1_w, no1_b, no_g, no_bt, no2_w, no2_b,
                         sp1_w, sp1_b, sp_g, sp_bt, sp2_w, sp2_b,
                         out, out + 32768);
}